// round 11
// baseline (speedup 1.0000x reference)
#include <cuda_runtime.h>
#include <cuda_fp16.h>

#define N_NODES 100000
#define D_FEAT  128
#define N_EDGES 1600000
#define EPS_F   1e-12f

#define EDGE_BLOCKS  1184
#define EDGE_THREADS 256

// Normalized node features quantized to int8 (x127).
// 1 row = 128 int8 = 128B = 8 x uint4. 100000 rows = 12.8 MB (L2-resident).
__device__ unsigned g_i8[(size_t)N_NODES * 32];
__device__ double   g_accum;   // static-init 0; reset by last edge block each run
__device__ unsigned g_done;    // ditto
__device__ int      g_idx64;   // 1 if edge_index is int64, 0 if int32

// Signed dp4a (force the int overload; table holds SIGNED int8).
__device__ __forceinline__ int dp4s(unsigned a, unsigned b, int c) {
    return __dp4a((int)a, (int)b, c);
}

// ---------------------------------------------------------------------------
// Kernel 1: normalize rows -> int8 table. Block 0 thread 0 also detects the
// index dtype (int64 LE with values < 100000 => every odd 32-bit word is 0).
// ---------------------------------------------------------------------------
__global__ void norm_kernel(const float* __restrict__ states,
                            const unsigned* __restrict__ eidx_words) {
    if (blockIdx.x == 0 && threadIdx.x == 0) {
        unsigned acc = 0;
        #pragma unroll
        for (int i = 0; i < 64; i++) acc |= eidx_words[2 * i + 1];
        g_idx64 = (acc == 0u) ? 1 : 0;
    }

    int gwarp = (blockIdx.x * blockDim.x + threadIdx.x) >> 5;
    int lane  = threadIdx.x & 31;
    if (gwarp >= N_NODES) return;

    float4 v = reinterpret_cast<const float4*>(states + (size_t)gwarp * D_FEAT)[lane];

    float ss = v.x * v.x + v.y * v.y + v.z * v.z + v.w * v.w;
    #pragma unroll
    for (int o = 16; o > 0; o >>= 1)
        ss += __shfl_xor_sync(0xffffffffu, ss, o);

    float scale = 127.0f / (sqrtf(ss) + EPS_F);

    int q0 = __float2int_rn(v.x * scale);
    int q1 = __float2int_rn(v.y * scale);
    int q2 = __float2int_rn(v.z * scale);
    int q3 = __float2int_rn(v.w * scale);
    unsigned p = (unsigned)(q0 & 0xff)
               | ((unsigned)(q1 & 0xff) << 8)
               | ((unsigned)(q2 & 0xff) << 16)
               | ((unsigned)(q3 & 0xff) << 24);
    g_i8[(size_t)gwarp * 32 + lane] = p;
}

// ---------------------------------------------------------------------------
// Kernel 2: edge loss. Each warp takes contiguous 32-edge chunks (grid-stride).
// Lanes cooperatively load s/d/w coalesced (streaming __ldcs), with the NEXT
// chunk's loads prefetched before processing the current chunk so their
// latency overlaps the 16 in-flight gathers. 4 edges per step: q = lane>>3
// selects the edge, k = lane&7 the 16B segment. Row gathers use __ldcg
// (L2-only: ~0 L1 hit rate for random gathers, skip dead L1 fills).
// Loss linearity: sum(ew*(1-sim)) = sum(ew) - sum(ew*sim)/127^2.
// One warp reduction at the end; last block finalizes and self-resets.
// ---------------------------------------------------------------------------
template <typename IdxT>
__device__ __forceinline__ void edge_chunks(const float* __restrict__ ew,
                                            const IdxT* __restrict__ eidx,
                                            int gwarp, int nwarps, int lane,
                                            float& acc_sim, float& acc_w) {
    const uint4* tab = reinterpret_cast<const uint4*>(g_i8);
    const int q = lane >> 3;       // edge within group of 4
    const int k = lane & 7;        // 16B segment within row
    const int nchunks = N_EDGES / 32;   // 50000, exact

    int c = gwarp;
    if (c >= nchunks) return;

    IdxT  s_my = __ldcs(&eidx[c * 32 + lane]);
    IdxT  d_my = __ldcs(&eidx[N_EDGES + c * 32 + lane]);
    float w_my = __ldcs(&ew[c * 32 + lane]);

    for (; c < nchunks; c += nwarps) {
        // Prefetch next chunk's coalesced loads; latency hides under gathers.
        int cn = c + nwarps;
        IdxT  s_nx = 0, d_nx = 0;
        float w_nx = 0.0f;
        if (cn < nchunks) {
            s_nx = __ldcs(&eidx[cn * 32 + lane]);
            d_nx = __ldcs(&eidx[N_EDGES + cn * 32 + lane]);
            w_nx = __ldcs(&ew[cn * 32 + lane]);
        }

        acc_w += w_my;

        #pragma unroll
        for (int j = 0; j < 8; j++) {
            int src = 4 * j + q;
            int   sj = (int)__shfl_sync(0xffffffffu, s_my, src);
            int   dj = (int)__shfl_sync(0xffffffffu, d_my, src);
            float wj = __shfl_sync(0xffffffffu, w_my, src);

            uint4 a = __ldcg(&tab[(size_t)sj * 8 + k]);
            uint4 b = __ldcg(&tab[(size_t)dj * 8 + k]);

            int id = dp4s(a.x, b.x,
                     dp4s(a.y, b.y,
                     dp4s(a.z, b.z,
                     dp4s(a.w, b.w, 0))));
            acc_sim += wj * (float)id;
        }

        s_my = s_nx; d_my = d_nx; w_my = w_nx;
    }
}

__global__ void __launch_bounds__(EDGE_THREADS)
edge_kernel(const float* __restrict__ ew,
            const void* __restrict__ eidx_raw,
            float* __restrict__ out) {
    const int lane   = threadIdx.x & 31;
    const int wib    = threadIdx.x >> 5;
    const int nwb    = EDGE_THREADS / 32;
    const int gwarp  = blockIdx.x * nwb + wib;
    const int nwarps = gridDim.x * nwb;

    float acc_sim = 0.0f;   // per-lane sum of wj * idot_partial
    float acc_w   = 0.0f;   // per-lane sum of its own chunk weights

    if (g_idx64)
        edge_chunks<long long>(ew, (const long long*)eidx_raw,
                               gwarp, nwarps, lane, acc_sim, acc_w);
    else
        edge_chunks<int>(ew, (const int*)eidx_raw,
                         gwarp, nwarps, lane, acc_sim, acc_w);

    // lane-partial of sum(ew*(1-sim)) with the 1/127^2 dequant folded in
    float diff = acc_w - acc_sim * (1.0f / 16129.0f);
    #pragma unroll
    for (int o = 16; o > 0; o >>= 1)
        diff += __shfl_xor_sync(0xffffffffu, diff, o);

    __shared__ float ssum[nwb <= 32 ? 32 : nwb];
    if (lane == 0) ssum[wib] = diff;
    __syncthreads();

    if (threadIdx.x == 0) {
        float t = 0.0f;
        #pragma unroll
        for (int i = 0; i < nwb; i++) t += ssum[i];
        atomicAdd(&g_accum, (double)t);
        __threadfence();
        unsigned done = atomicAdd(&g_done, 1u);
        if (done == gridDim.x - 1) {
            double total = atomicAdd(&g_accum, 0.0);
            out[0] = (float)(total / (double)N_EDGES);
            g_accum = 0.0;              // reset for next graph replay
            g_done  = 0u;
        }
    }
}

extern "C" void kernel_launch(void* const* d_in, const int* in_sizes, int n_in,
                              void* d_out, int out_size) {
    // Identify inputs by element count:
    //   states      : 12,800,000   edge_weight : 1,600,000
    //   edge_index  : 3,200,000 (int32 or int64 -- detected on device)
    const float* states   = nullptr;
    const float* ew       = nullptr;
    const void*  eidx_raw = nullptr;

    for (int i = 0; i < n_in; i++) {
        if (in_sizes[i] == (int)((size_t)N_NODES * D_FEAT)) states = (const float*)d_in[i];
        else if (in_sizes[i] == N_EDGES)                    ew = (const float*)d_in[i];
        else if (in_sizes[i] == 2 * N_EDGES)                eidx_raw = d_in[i];
    }
    if (!states || !ew || !eidx_raw) {   // positional fallback
        states   = (const float*)d_in[0];
        ew       = (const float*)d_in[1];
        eidx_raw = d_in[2];
    }

    float* out = (float*)d_out;
    (void)out_size;

    // 100000 warps, 8 per block.
    norm_kernel<<<(N_NODES + 7) / 8, 256>>>(states, (const unsigned*)eidx_raw);

    // Persistent edge kernel: 1184 blocks x 256 thr (~64 warps/SM on 148 SMs).
    edge_kernel<<<EDGE_BLOCKS, EDGE_THREADS>>>(ew, eidx_raw, out);
}

// round 12
// speedup vs baseline: 1.1193x; 1.1193x over previous
#include <cuda_runtime.h>
#include <cuda_fp16.h>

#define N_NODES 100000
#define D_FEAT  128
#define N_EDGES 1600000
#define EPS_F   1e-12f

#define EDGE_BLOCKS  1184
#define EDGE_THREADS 256

// Normalized node features quantized to int8 (x127).
// 1 row = 128 int8 = 128B = 8 x uint4. 100000 rows = 12.8 MB (L2-resident).
__device__ unsigned g_i8[(size_t)N_NODES * 32];
__device__ double   g_accum;   // static-init 0; reset by last edge block each run
__device__ unsigned g_done;    // ditto
__device__ int      g_idx64;   // 1 if edge_index is int64, 0 if int32

// Signed dp4a (force the int overload; table holds SIGNED int8).
__device__ __forceinline__ int dp4s(unsigned a, unsigned b, int c) {
    return __dp4a((int)a, (int)b, c);
}

// ---------------------------------------------------------------------------
// Kernel 1: normalize rows -> int8 table. Block 0 thread 0 also detects the
// index dtype (int64 LE with values < 100000 => every odd 32-bit word is 0).
// ---------------------------------------------------------------------------
__global__ void norm_kernel(const float* __restrict__ states,
                            const unsigned* __restrict__ eidx_words) {
    if (blockIdx.x == 0 && threadIdx.x == 0) {
        unsigned acc = 0;
        #pragma unroll
        for (int i = 0; i < 64; i++) acc |= eidx_words[2 * i + 1];
        g_idx64 = (acc == 0u) ? 1 : 0;
    }

    int gwarp = (blockIdx.x * blockDim.x + threadIdx.x) >> 5;
    int lane  = threadIdx.x & 31;
    if (gwarp >= N_NODES) return;

    float4 v = reinterpret_cast<const float4*>(states + (size_t)gwarp * D_FEAT)[lane];

    float ss = v.x * v.x + v.y * v.y + v.z * v.z + v.w * v.w;
    #pragma unroll
    for (int o = 16; o > 0; o >>= 1)
        ss += __shfl_xor_sync(0xffffffffu, ss, o);

    float scale = 127.0f / (sqrtf(ss) + EPS_F);

    int q0 = __float2int_rn(v.x * scale);
    int q1 = __float2int_rn(v.y * scale);
    int q2 = __float2int_rn(v.z * scale);
    int q3 = __float2int_rn(v.w * scale);
    unsigned p = (unsigned)(q0 & 0xff)
               | ((unsigned)(q1 & 0xff) << 8)
               | ((unsigned)(q2 & 0xff) << 16)
               | ((unsigned)(q3 & 0xff) << 24);
    g_i8[(size_t)gwarp * 32 + lane] = p;
}

// ---------------------------------------------------------------------------
// Kernel 2: edge loss. Each warp takes contiguous 32-edge chunks (grid-stride).
// Lanes cooperatively load s/d/w coalesced (__ldcs streaming), then process
// 4 edges per step: q = lane>>3 selects the edge, k = lane&7 the 16B segment.
// Row gathers use __ldcg (L2-only: ~0 L1 hit rate for random gathers).
// NO software prefetch: R11 showed it costs 8 regs -> occupancy 91%->61%
// -> regression. Warp count is the latency-hiding mechanism here.
// Loss linearity: sum(ew*(1-sim)) = sum(ew) - sum(ew*sim)/127^2.
// One warp reduction at the end; last block finalizes and self-resets.
// ---------------------------------------------------------------------------
template <typename IdxT>
__device__ __forceinline__ void edge_chunks(const float* __restrict__ ew,
                                            const IdxT* __restrict__ eidx,
                                            int gwarp, int nwarps, int lane,
                                            float& acc_sim, float& acc_w) {
    const uint4* tab = reinterpret_cast<const uint4*>(g_i8);
    const int q = lane >> 3;       // edge within group of 4
    const int k = lane & 7;        // 16B segment within row
    const int nchunks = N_EDGES / 32;   // 50000, exact

    for (int c = gwarp; c < nchunks; c += nwarps) {
        int base = c * 32;
        IdxT  s_my = __ldcs(&eidx[base + lane]);
        IdxT  d_my = __ldcs(&eidx[N_EDGES + base + lane]);
        float w_my = __ldcs(&ew[base + lane]);
        acc_w += w_my;

        #pragma unroll
        for (int j = 0; j < 8; j++) {
            int src = 4 * j + q;
            int   sj = (int)__shfl_sync(0xffffffffu, s_my, src);
            int   dj = (int)__shfl_sync(0xffffffffu, d_my, src);
            float wj = __shfl_sync(0xffffffffu, w_my, src);

            uint4 a = __ldcg(&tab[(size_t)sj * 8 + k]);
            uint4 b = __ldcg(&tab[(size_t)dj * 8 + k]);

            int id = dp4s(a.x, b.x,
                     dp4s(a.y, b.y,
                     dp4s(a.z, b.z,
                     dp4s(a.w, b.w, 0))));
            acc_sim += wj * (float)id;
        }
    }
}

// minBlocksPerMultiprocessor=8 pins ptxas to <=32 regs -> 64 warps/SM.
__global__ void __launch_bounds__(EDGE_THREADS, 8)
edge_kernel(const float* __restrict__ ew,
            const void* __restrict__ eidx_raw,
            float* __restrict__ out) {
    const int lane   = threadIdx.x & 31;
    const int wib    = threadIdx.x >> 5;
    const int nwb    = EDGE_THREADS / 32;
    const int gwarp  = blockIdx.x * nwb + wib;
    const int nwarps = gridDim.x * nwb;

    float acc_sim = 0.0f;   // per-lane sum of wj * idot_partial
    float acc_w   = 0.0f;   // per-lane sum of its own chunk weights

    if (g_idx64)
        edge_chunks<long long>(ew, (const long long*)eidx_raw,
                               gwarp, nwarps, lane, acc_sim, acc_w);
    else
        edge_chunks<int>(ew, (const int*)eidx_raw,
                         gwarp, nwarps, lane, acc_sim, acc_w);

    // lane-partial of sum(ew*(1-sim)) with the 1/127^2 dequant folded in
    float diff = acc_w - acc_sim * (1.0f / 16129.0f);
    #pragma unroll
    for (int o = 16; o > 0; o >>= 1)
        diff += __shfl_xor_sync(0xffffffffu, diff, o);

    __shared__ float ssum[nwb <= 32 ? 32 : nwb];
    if (lane == 0) ssum[wib] = diff;
    __syncthreads();

    if (threadIdx.x == 0) {
        float t = 0.0f;
        #pragma unroll
        for (int i = 0; i < nwb; i++) t += ssum[i];
        atomicAdd(&g_accum, (double)t);
        __threadfence();
        unsigned done = atomicAdd(&g_done, 1u);
        if (done == gridDim.x - 1) {
            double total = atomicAdd(&g_accum, 0.0);
            out[0] = (float)(total / (double)N_EDGES);
            g_accum = 0.0;              // reset for next graph replay
            g_done  = 0u;
        }
    }
}

extern "C" void kernel_launch(void* const* d_in, const int* in_sizes, int n_in,
                              void* d_out, int out_size) {
    // Identify inputs by element count:
    //   states      : 12,800,000   edge_weight : 1,600,000
    //   edge_index  : 3,200,000 (int32 or int64 -- detected on device)
    const float* states   = nullptr;
    const float* ew       = nullptr;
    const void*  eidx_raw = nullptr;

    for (int i = 0; i < n_in; i++) {
        if (in_sizes[i] == (int)((size_t)N_NODES * D_FEAT)) states = (const float*)d_in[i];
        else if (in_sizes[i] == N_EDGES)                    ew = (const float*)d_in[i];
        else if (in_sizes[i] == 2 * N_EDGES)                eidx_raw = d_in[i];
    }
    if (!states || !ew || !eidx_raw) {   // positional fallback
        states   = (const float*)d_in[0];
        ew       = (const float*)d_in[1];
        eidx_raw = d_in[2];
    }

    float* out = (float*)d_out;
    (void)out_size;

    // 100000 warps, 8 per block.
    norm_kernel<<<(N_NODES + 7) / 8, 256>>>(states, (const unsigned*)eidx_raw);

    // Persistent edge kernel: 1184 blocks x 256 thr (~64 warps/SM on 148 SMs).
    edge_kernel<<<EDGE_BLOCKS, EDGE_THREADS>>>(ew, eidx_raw, out);
}